// round 4
// baseline (speedup 1.0000x reference)
#include <cuda_runtime.h>
#include <cuda_bf16.h>
#include <math_constants.h>
#include <stdint.h>

// Problem shape (fixed by the dataset)
constexpr int B       = 4;
constexpr int N       = 32768;
constexpr int NQ      = 2048;
constexpr int K       = 16;
constexpr int QSTRIDE = N / NQ;   // 16

constexpr int TILE = 8192;            // candidate points per smem tile
constexpr int WPB  = 8;               // warps (queries) per block
constexpr int THREADS = WPB * 32;     // 256
constexpr int SMEM_BYTES = TILE * 3 * sizeof(float);  // 96 KB

// One warp per query. Each lane scans an interleaved 1/32 partition of the
// candidate set keeping a sorted top-K in registers, then the warp merges
// 32 sorted lists with an exact (d, idx)-lexicographic arg-min, matching
// jax.lax.top_k ordering (ascending distance, ties -> smaller index).
__global__ __launch_bounds__(THREADS, 2)
void knn_kernel(const float* __restrict__ xyz,
                float* __restrict__ out) {   // [idx: B*NQ*K][pts: B*NQ*3], all fp32
    extern __shared__ float s[];   // TILE*3 floats, raw float3 layout

    const int lane = threadIdx.x & 31;
    const int warp = threadIdx.x >> 5;
    const int qg   = blockIdx.x * WPB + warp;     // global query id, 0..B*NQ-1
    const int b    = qg >> 11;                    // / NQ (NQ = 2048)
    const int q    = qg & (NQ - 1);

    const float* __restrict__ base = xyz + (size_t)b * N * 3;
    const int qidx = q * QSTRIDE;

    const float qx = base[qidx * 3 + 0];
    const float qy = base[qidx * 3 + 1];
    const float qz = base[qidx * 3 + 2];

    // Per-lane sorted top-K (ascending distance)
    float bd[K];
    int   bi[K];
#pragma unroll
    for (int k = 0; k < K; ++k) { bd[k] = CUDART_INF_F; bi[k] = 0x7fffffff; }

    for (int t = 0; t < N; t += TILE) {
        __syncthreads();
        // Cooperative tile load: TILE*3 contiguous floats, vectorized
        {
            const float4* __restrict__ g = (const float4*)(base + (size_t)t * 3);
            float4* sm4 = (float4*)s;
#pragma unroll
            for (int k = threadIdx.x; k < (TILE * 3) / 4; k += THREADS)
                sm4[k] = g[k];
        }
        __syncthreads();

        // Lane-interleaved scan: word index 3*(j*32+lane)+c -> banks
        // (3*lane + c) mod 32, conflict-free (gcd(3,32)=1).
        const float* __restrict__ sp = s + 3 * lane;
#pragma unroll 4
        for (int j = 0; j < TILE / 32; ++j) {
            const float px = sp[96 * j + 0];
            const float py = sp[96 * j + 1];
            const float pz = sp[96 * j + 2];
            // Bit-exact with reference fp32: no FMA contraction,
            // association ((dx^2 + dy^2) + dz^2).
            const float dx = __fsub_rn(qx, px);
            const float dy = __fsub_rn(qy, py);
            const float dz = __fsub_rn(qz, pz);
            const float d  = __fadd_rn(__fadd_rn(__fmul_rn(dx, dx),
                                                 __fmul_rn(dy, dy)),
                                       __fmul_rn(dz, dz));
            if (d < bd[K - 1]) {
                // Replace worst and bubble up (strict <, so equal-distance
                // earlier (smaller) indices stay ranked first).
                bd[K - 1] = d;
                bi[K - 1] = t + j * 32 + lane;
#pragma unroll
                for (int k = K - 1; k > 0; --k) {
                    if (bd[k] < bd[k - 1]) {
                        float td = bd[k]; bd[k] = bd[k - 1]; bd[k - 1] = td;
                        int   ti = bi[k]; bi[k] = bi[k - 1]; bi[k - 1] = ti;
                    }
                }
            }
        }
    }

    // Warp merge: 16 rounds of lexicographic (d, idx) arg-min over 32 lane
    // cursors. Keys are unique (disjoint index partitions) so the winner
    // lane is unambiguous.
    int cur = 0;
    int out_i = 0;   // lane r holds winner of round r
#pragma unroll
    for (int r = 0; r < K; ++r) {
        float vd = (cur < K) ? bd[cur] : CUDART_INF_F;
        int   vi = (cur < K) ? bi[cur] : 0x7fffffff;
        int   vl = lane;
#pragma unroll
        for (int off = 16; off > 0; off >>= 1) {
            const float od = __shfl_xor_sync(0xffffffffu, vd, off);
            const int   oi = __shfl_xor_sync(0xffffffffu, vi, off);
            const int   ol = __shfl_xor_sync(0xffffffffu, vl, off);
            if (od < vd || (od == vd && oi < vi)) { vd = od; vi = oi; vl = ol; }
        }
        if (lane == vl) ++cur;        // winner lane consumes its head
        if (lane == r)  out_i = vi;   // round-r winner kept by lane r
    }

    // Output 0: idx, shape (B, NQ, K, 1), written as float32 (values < 2^15,
    // exactly representable). Output 1: pts, shape (B, NQ, 3), float32.
    float* __restrict__ out_idx = out;
    float* __restrict__ out_pts = out + (size_t)B * NQ * K;

    if (lane < K)
        out_idx[(size_t)qg * K + lane] = (float)out_i;
    if (lane == 0) {
        out_pts[(size_t)qg * 3 + 0] = qx;
        out_pts[(size_t)qg * 3 + 1] = qy;
        out_pts[(size_t)qg * 3 + 2] = qz;
    }
}

extern "C" void kernel_launch(void* const* d_in, const int* in_sizes, int n_in,
                              void* d_out, int out_size) {
    (void)in_sizes; (void)n_in; (void)out_size;
    const float* xyz = (const float*)d_in[0];
    float* out = (float*)d_out;

    static bool attr_set = false;
    if (!attr_set) {
        cudaFuncSetAttribute(knn_kernel,
                             cudaFuncAttributeMaxDynamicSharedMemorySize,
                             SMEM_BYTES);
        attr_set = true;
    }

    const int grid = (B * NQ) / WPB;   // 1024 blocks
    knn_kernel<<<grid, THREADS, SMEM_BYTES>>>(xyz, out);
}

// round 8
// speedup vs baseline: 8.6719x; 8.6719x over previous
#include <cuda_runtime.h>
#include <stdint.h>

// Problem shape (fixed by the dataset)
constexpr int B       = 4;
constexpr int N       = 32768;
constexpr int NQ      = 2048;
constexpr int K       = 16;
constexpr int QSTRIDE = N / NQ;   // 16

constexpr int TILE    = 2048;          // candidate points per smem tile
constexpr int WPB     = 8;             // warps (queries) per block
constexpr int THREADS = WPB * 32;      // 256

typedef unsigned long long u64;
typedef unsigned int u32;

constexpr u64 KEY_INF = ~0ULL;

// One warp per query. Lane j processes candidate (tile + iter*32 + j).
// The warp maintains a DISTRIBUTED sorted top-16 list: lane i holds list
// element i as a u64 key (hi = fp32 bits of distance, lo = index), so a
// single u64 compare gives the exact (d asc, idx asc) order that
// jax.lax.top_k uses. A candidate enters only if it beats the global 16th
// best (lane 15's key), which makes insertions RARE (~8% of iterations)
// instead of nearly-every-iteration as with per-lane lists.
__global__ __launch_bounds__(THREADS, 4)
void knn_kernel(const float* __restrict__ xyz, float* __restrict__ out) {
    __shared__ float4 s[TILE];

    const int lane = threadIdx.x & 31;
    const int warp = threadIdx.x >> 5;
    const int qg   = blockIdx.x * WPB + warp;   // global query id
    const int b    = qg >> 11;                  // / NQ
    const int q    = qg & (NQ - 1);

    const float* __restrict__ base = xyz + (size_t)b * N * 3;
    const int qidx = q * QSTRIDE;

    const float qx = base[qidx * 3 + 0];
    const float qy = base[qidx * 3 + 1];
    const float qz = base[qidx * 3 + 2];

    u64   L    = KEY_INF;                        // my element of the warp list
    u64   Tkey = KEY_INF;                        // list element 15 (16th best)
    float Td   = __int_as_float(0x7f800000);     // its distance (+inf)

    for (int t = 0; t < N; t += TILE) {
        __syncthreads();
        // Cooperative tile load, float3 -> padded float4 (coalesced LDG.32s)
        for (int i = threadIdx.x; i < TILE; i += THREADS) {
            const float* __restrict__ p = base + (size_t)(t + i) * 3;
            s[i] = make_float4(p[0], p[1], p[2], 0.0f);
        }
        __syncthreads();

#pragma unroll 2
        for (int j = 0; j < TILE / 32; ++j) {
            const float4 p = s[j * 32 + lane];
            // Bit-exact with reference fp32: no FMA contraction,
            // association ((dx^2 + dy^2) + dz^2), all round-to-nearest.
            const float dx = __fsub_rn(qx, p.x);
            const float dy = __fsub_rn(qy, p.y);
            const float dz = __fsub_rn(qz, p.z);
            const float d  = __fadd_rn(__fadd_rn(__fmul_rn(dx, dx),
                                                 __fmul_rn(dy, dy)),
                                       __fmul_rn(dz, dz));
            // Cheap pre-filter: d <= Td (d == Td resolved exactly below).
            if (__any_sync(0xffffffffu, d <= Td)) {
                const int cidx = t + j * 32 + lane;
                const u64 ck = ((u64)__float_as_uint(d) << 32) | (u32)cidx;
                const bool valid = ck < Tkey;   // exact lexicographic test
                u64 nk = valid ? ck : KEY_INF;
                u32 m = __ballot_sync(0xffffffffu, valid);
                if (m) {
                    if (__popc(m) <= 2) {
                        // Sequential distributed shift-insert (1-2 keys).
                        while (m) {
                            const int src = __ffs(m) - 1;
                            m &= m - 1;
                            const u64 nkk = __shfl_sync(0xffffffffu, nk, src);
                            const u64 up  = __shfl_up_sync(0xffffffffu, L, 1);
                            const bool lt  = nkk < L;
                            const bool ltp = (lane > 0) && (nkk < up);
                            if (lt) L = ltp ? up : nkk;
                        }
                    } else {
                        // Full path: bitonic sort the 32 candidate keys asc.
#pragma unroll
                        for (int k2 = 2; k2 <= 32; k2 <<= 1) {
#pragma unroll
                            for (int j2 = k2 >> 1; j2 >= 1; j2 >>= 1) {
                                const u64 o = __shfl_xor_sync(0xffffffffu, nk, j2);
                                const bool takemin =
                                    ((lane & j2) == 0) == ((lane & k2) == 0);
                                const bool pl = nk < o;
                                nk = (pl == takemin) ? nk : o;
                            }
                        }
                        // Merge: old (asc) vs new reversed (desc); elementwise
                        // min keeps the 32 smallest as a bitonic sequence.
                        const u64 r = __shfl_sync(0xffffffffu, nk, 31 - lane);
                        L = (L < r) ? L : r;
                        // Clean-up bitonic merge -> fully ascending.
#pragma unroll
                        for (int j2 = 16; j2 >= 1; j2 >>= 1) {
                            const u64 o = __shfl_xor_sync(0xffffffffu, L, j2);
                            const bool takemin = ((lane & j2) == 0);
                            const bool pl = L < o;
                            L = (pl == takemin) ? L : o;
                        }
                    }
                    // Re-broadcast the 16th-best key/threshold.
                    Tkey = __shfl_sync(0xffffffffu, L, 15);
                    u32 thi = (u32)(Tkey >> 32);
                    if (thi > 0x7f800000u) thi = 0x7f800000u;  // sentinel -> +inf
                    Td = __uint_as_float(thi);
                }
            }
        }
    }

    // Output 0: idx, shape (B, NQ, K, 1), values exactly representable in fp32.
    // Output 1: pts, shape (B, NQ, 3).
    float* __restrict__ out_idx = out;
    float* __restrict__ out_pts = out + (size_t)B * NQ * K;

    if (lane < K)
        out_idx[(size_t)qg * K + lane] = (float)(u32)(L & 0xffffffffu);
    if (lane == 0) {
        out_pts[(size_t)qg * 3 + 0] = qx;
        out_pts[(size_t)qg * 3 + 1] = qy;
        out_pts[(size_t)qg * 3 + 2] = qz;
    }
}

extern "C" void kernel_launch(void* const* d_in, const int* in_sizes, int n_in,
                              void* d_out, int out_size) {
    (void)in_sizes; (void)n_in; (void)out_size;
    const float* xyz = (const float*)d_in[0];
    float* out = (float*)d_out;

    const int grid = (B * NQ) / WPB;   // 1024 blocks
    knn_kernel<<<grid, THREADS>>>(xyz, out);
}

// round 10
// speedup vs baseline: 10.6694x; 1.2303x over previous
#include <cuda_runtime.h>
#include <stdint.h>

// Problem shape (fixed by the dataset)
constexpr int B       = 4;
constexpr int N       = 32768;
constexpr int NQ      = 2048;
constexpr int K       = 16;
constexpr int QSTRIDE = N / NQ;   // 16

constexpr int TILE    = 1024;          // candidate points per smem tile
constexpr int WPB     = 4;             // warps per block
constexpr int QPW     = 2;             // queries per warp
constexpr int THREADS = WPB * 32;      // 128
constexpr int QPB     = WPB * QPW;     // 8 queries per block
constexpr int BLOCKS_PER_BATCH = NQ / QPB;  // 256

typedef unsigned long long u64;
typedef unsigned int u32;

constexpr u64 KEY_INF = ~0ULL;
constexpr u32 FULL    = 0xffffffffu;

// Insert up to 32 candidate keys (nk, invalid lanes = KEY_INF, mask m) into
// the warp-distributed sorted list L (lane i holds element i, ascending).
__device__ __forceinline__ void warp_insert(u64& L, u64 nk, u32 m, int lane) {
    if (__popc(m) <= 2) {
        // Sequential distributed shift-insert (1-2 keys).
        while (m) {
            const int src = __ffs(m) - 1;
            m &= m - 1;
            const u64 k  = __shfl_sync(FULL, nk, src);
            const u64 up = __shfl_up_sync(FULL, L, 1);
            if (k < L) L = (lane > 0 && k < up) ? up : k;
        }
    } else {
        // Bitonic sort the 32 candidate keys ascending.
#pragma unroll
        for (int k2 = 2; k2 <= 32; k2 <<= 1) {
#pragma unroll
            for (int j2 = k2 >> 1; j2 >= 1; j2 >>= 1) {
                const u64 o = __shfl_xor_sync(FULL, nk, j2);
                const bool takemin = ((lane & j2) == 0) == ((lane & k2) == 0);
                const bool pl = nk < o;
                nk = (pl == takemin) ? nk : o;
            }
        }
        // Merge old (asc) with new reversed (desc): elementwise min keeps
        // the 32 smallest as a bitonic sequence; clean-up merge sorts it.
        const u64 r = __shfl_sync(FULL, nk, 31 - lane);
        L = (L < r) ? L : r;
#pragma unroll
        for (int j2 = 16; j2 >= 1; j2 >>= 1) {
            const u64 o = __shfl_xor_sync(FULL, L, j2);
            const bool takemin = ((lane & j2) == 0);
            const bool pl = L < o;
            L = (pl == takemin) ? L : o;
        }
    }
}

__device__ __forceinline__ void refresh_threshold(const u64& L, u64& Tkey, float& Td) {
    Tkey = __shfl_sync(FULL, L, K - 1);
    u32 thi = (u32)(Tkey >> 32);
    if (thi > 0x7f800000u) thi = 0x7f800000u;   // sentinel bits -> +inf
    Td = __uint_as_float(thi);
}

// One warp handles TWO queries; lane j processes candidate (t + iter*32 + j)
// against both. The LDS, vote, branch and loop overhead are shared between
// the queries; exact (d asc, idx asc) jax.lax.top_k order is preserved via
// u64 keys (hi = fp32 bits of the bit-exact distance, lo = index).
__global__ __launch_bounds__(THREADS, 8)
void knn_kernel(const float* __restrict__ xyz, float* __restrict__ out) {
    __shared__ float4 s[TILE];

    const int lane  = threadIdx.x & 31;
    const int warp  = threadIdx.x >> 5;
    const int batch = blockIdx.x >> 8;                       // / BLOCKS_PER_BATCH
    const int q0    = (blockIdx.x & (BLOCKS_PER_BATCH - 1)) * QPB + warp * QPW;

    const float* __restrict__ base = xyz + (size_t)batch * N * 3;

    const float qx0 = base[(q0 + 0) * QSTRIDE * 3 + 0];
    const float qy0 = base[(q0 + 0) * QSTRIDE * 3 + 1];
    const float qz0 = base[(q0 + 0) * QSTRIDE * 3 + 2];
    const float qx1 = base[(q0 + 1) * QSTRIDE * 3 + 0];
    const float qy1 = base[(q0 + 1) * QSTRIDE * 3 + 1];
    const float qz1 = base[(q0 + 1) * QSTRIDE * 3 + 2];

    u64   L0 = KEY_INF, L1 = KEY_INF;
    u64   T0 = KEY_INF, T1 = KEY_INF;
    float Td0 = __int_as_float(0x7f800000);
    float Td1 = __int_as_float(0x7f800000);

    for (int t = 0; t < N; t += TILE) {
        __syncthreads();
        for (int i = threadIdx.x; i < TILE; i += THREADS) {
            const float* __restrict__ p = base + (size_t)(t + i) * 3;
            s[i] = make_float4(p[0], p[1], p[2], 0.0f);
        }
        __syncthreads();

#pragma unroll 4
        for (int j = 0; j < TILE / 32; ++j) {
            const float4 p = s[j * 32 + lane];
            // Bit-exact with reference fp32: no FMA contraction,
            // association ((dx^2 + dy^2) + dz^2), round-to-nearest.
            const float dx0 = __fsub_rn(qx0, p.x);
            const float dy0 = __fsub_rn(qy0, p.y);
            const float dz0 = __fsub_rn(qz0, p.z);
            const float dx1 = __fsub_rn(qx1, p.x);
            const float dy1 = __fsub_rn(qy1, p.y);
            const float dz1 = __fsub_rn(qz1, p.z);
            const float d0 = __fadd_rn(__fadd_rn(__fmul_rn(dx0, dx0),
                                                 __fmul_rn(dy0, dy0)),
                                       __fmul_rn(dz0, dz0));
            const float d1 = __fadd_rn(__fadd_rn(__fmul_rn(dx1, dx1),
                                                 __fmul_rn(dy1, dy1)),
                                       __fmul_rn(dz1, dz1));
            const bool pr0 = (d0 <= Td0);
            const bool pr1 = (d1 <= Td1);
            if (__any_sync(FULL, pr0 | pr1)) {
                const int cidx = t + j * 32 + lane;
                {
                    const u64 ck = ((u64)__float_as_uint(d0) << 32) | (u32)cidx;
                    const bool v = ck < T0;              // exact lexicographic
                    const u32 m = __ballot_sync(FULL, v);
                    if (m) {
                        warp_insert(L0, v ? ck : KEY_INF, m, lane);
                        refresh_threshold(L0, T0, Td0);
                    }
                }
                {
                    const u64 ck = ((u64)__float_as_uint(d1) << 32) | (u32)cidx;
                    const bool v = ck < T1;
                    const u32 m = __ballot_sync(FULL, v);
                    if (m) {
                        warp_insert(L1, v ? ck : KEY_INF, m, lane);
                        refresh_threshold(L1, T1, Td1);
                    }
                }
            }
        }
    }

    // Output 0: idx (B, NQ, K, 1) as fp32 (values < 2^15, exact).
    // Output 1: pts (B, NQ, 3) fp32.
    float* __restrict__ out_idx = out;
    float* __restrict__ out_pts = out + (size_t)B * NQ * K;

    const int qg0 = batch * NQ + q0;
    if (lane < K) {
        out_idx[(size_t)(qg0 + 0) * K + lane] = (float)(u32)(L0 & 0xffffffffu);
        out_idx[(size_t)(qg0 + 1) * K + lane] = (float)(u32)(L1 & 0xffffffffu);
    }
    if (lane == 0) {
        out_pts[(size_t)(qg0 + 0) * 3 + 0] = qx0;
        out_pts[(size_t)(qg0 + 0) * 3 + 1] = qy0;
        out_pts[(size_t)(qg0 + 0) * 3 + 2] = qz0;
        out_pts[(size_t)(qg0 + 1) * 3 + 0] = qx1;
        out_pts[(size_t)(qg0 + 1) * 3 + 1] = qy1;
        out_pts[(size_t)(qg0 + 1) * 3 + 2] = qz1;
    }
}

extern "C" void kernel_launch(void* const* d_in, const int* in_sizes, int n_in,
                              void* d_out, int out_size) {
    (void)in_sizes; (void)n_in; (void)out_size;
    const float* xyz = (const float*)d_in[0];
    float* out = (float*)d_out;

    const int grid = B * BLOCKS_PER_BATCH;   // 1024 blocks
    knn_kernel<<<grid, THREADS>>>(xyz, out);
}